// round 16
// baseline (speedup 1.0000x reference)
#include <cuda_runtime.h>
#include <cuda_fp16.h>
#include <math.h>
#include <stdint.h>

#define BB   16
#define LL   512
#define DD   768
#define HH   12
#define KDIM 64
#define FFD  3072
#define NLAY 12
#define NCLS 4
#define NTOK (BB*LL)   // 8192
#define QKVN 2304

// ---------------- scratch ----------------
__device__ float g_h [NTOK*DD];
__device__ float g_t2[NTOK*DD];
__device__ float g_scores[(size_t)BB*HH*LL*LL];     // fp32 S (layer-0 only)
__device__ int   g_mixpos[NTOK];
__device__ float g_pooled[BB*DD];
__device__ float g_part[BB*16*DD];

__device__ __half g_hh[NTOK*DD],  g_hl[NTOK*DD];
__device__ __half g_qkvh[(size_t)NTOK*QKVN], g_qkvl[(size_t)NTOK*QKVN];
__device__ __half g_oh[NTOK*DD],  g_ol[NTOK*DD];
__device__ __half g_t1h[(size_t)NTOK*FFD], g_t1l[(size_t)NTOK*FFD];
__device__ __half g_Sp[(size_t)BB*HH*LL*LL];        // softmax probs (fp16)
__device__ __half g_Slog[(size_t)BB*HH*LL*LL];      // fp16 logits (standard layers)

// packed / split weights
__device__ __half g_Wqkvh[(size_t)NLAY*DD*QKVN], g_Wqkvl[(size_t)NLAY*DD*QKVN];
__device__ float  g_bqkv[NLAY*QKVN];
__device__ __half g_Woh[NLAY*DD*DD],  g_Wol[NLAY*DD*DD];
__device__ __half g_Wf1h[(size_t)NLAY*DD*FFD], g_Wf1l[(size_t)NLAY*DD*FFD];
__device__ __half g_Wf2h[(size_t)NLAY*DD*FFD], g_Wf2l[(size_t)NLAY*DD*FFD];

__device__ __forceinline__ uint32_t smem_u32(const void* p){
  uint32_t a;
  asm("{ .reg .u64 t; cvta.to.shared.u64 t, %1; cvt.u32.u64 %0, t; }" : "=r"(a) : "l"(p));
  return a;
}
__device__ __forceinline__ void mma_f16(float* d, const uint32_t* a, const uint32_t* b){
  asm volatile(
    "mma.sync.aligned.m16n8k16.row.col.f32.f16.f16.f32 "
    "{%0,%1,%2,%3},{%4,%5,%6,%7},{%8,%9},{%0,%1,%2,%3};"
    : "+f"(d[0]), "+f"(d[1]), "+f"(d[2]), "+f"(d[3])
    : "r"(a[0]), "r"(a[1]), "r"(a[2]), "r"(a[3]), "r"(b[0]), "r"(b[1]));
}
__device__ __forceinline__ void mma_f16acc(uint32_t* d, const uint32_t* a, const uint32_t* b){
  asm volatile(
    "mma.sync.aligned.m16n8k16.row.col.f16.f16.f16.f16 "
    "{%0,%1},{%2,%3,%4,%5},{%6,%7},{%0,%1};"
    : "+r"(d[0]), "+r"(d[1])
    : "r"(a[0]), "r"(a[1]), "r"(a[2]), "r"(a[3]), "r"(b[0]), "r"(b[1]));
}
__device__ __forceinline__ void ldmat4(uint32_t* r, uint32_t addr){
  asm volatile("ldmatrix.sync.aligned.m8n8.x4.shared.b16 {%0,%1,%2,%3}, [%4];"
    : "=r"(r[0]), "=r"(r[1]), "=r"(r[2]), "=r"(r[3]) : "r"(addr));
}
__device__ __forceinline__ void ldmat4t(uint32_t* r, uint32_t addr){
  asm volatile("ldmatrix.sync.aligned.m8n8.x4.trans.shared.b16 {%0,%1,%2,%3}, [%4];"
    : "=r"(r[0]), "=r"(r[1]), "=r"(r[2]), "=r"(r[3]) : "r"(addr));
}
__device__ __forceinline__ void split2(float x, __half& h, __half& l){
  h = __float2half_rn(x);
  l = __float2half_rn((x - __half2float(h)) * 4096.0f);
}
#define LOSCL (1.0f/4096.0f)

// ---------------- weight prep kernels ----------------
__global__ void __launch_bounds__(256) split_w(const float4* __restrict__ src,
    __half2* __restrict__ hi, __half2* __restrict__ lo, int n4){
  int i = blockIdx.x*256 + threadIdx.x;
  if (i >= n4) return;
  float4 v = src[i];
  __half hx,lx,hy,ly,hz,lz,hw,lw;
  split2(v.x,hx,lx); split2(v.y,hy,ly); split2(v.z,hz,lz); split2(v.w,hw,lw);
  hi[2*(size_t)i]   = __halves2half2(hx,hy);
  hi[2*(size_t)i+1] = __halves2half2(hz,hw);
  lo[2*(size_t)i]   = __halves2half2(lx,ly);
  lo[2*(size_t)i+1] = __halves2half2(lz,lw);
}

__global__ void __launch_bounds__(256) split_w2(
    const float4* __restrict__ s0, __half2* __restrict__ h0, __half2* __restrict__ l0,
    const float4* __restrict__ s1, __half2* __restrict__ h1, __half2* __restrict__ l1,
    int n4){
  int i = blockIdx.x*256 + threadIdx.x;
  if (i >= n4) return;
  const float4* s = blockIdx.y ? s1 : s0;
  __half2* hh = blockIdx.y ? h1 : h0;
  __half2* ll = blockIdx.y ? l1 : l0;
  float4 v = s[i];
  __half hx,lx,hy,ly,hz,lz,hw,lw;
  split2(v.x,hx,lx); split2(v.y,hy,ly); split2(v.z,hz,lz); split2(v.w,hw,lw);
  hh[2*(size_t)i]   = __halves2half2(hx,hy);
  hh[2*(size_t)i+1] = __halves2half2(hz,hw);
  ll[2*(size_t)i]   = __halves2half2(lx,ly);
  ll[2*(size_t)i+1] = __halves2half2(lz,lw);
}

__global__ void __launch_bounds__(256) pack_qkv(
    const float4* __restrict__ Wq, const float4* __restrict__ Wk,
    const float4* __restrict__ Wv,
    __half2* __restrict__ dh, __half2* __restrict__ dl, int total4){
  int i = blockIdx.x*256 + threadIdx.x;
  if (i >= total4) return;
  int row = i / 576, cw = i % 576;
  int third = cw / 192, c4 = cw % 192;
  const float4* src = (third == 0) ? Wq : (third == 1) ? Wk : Wv;
  float4 v = src[(size_t)row*192 + c4];
  __half hx,lx,hy,ly,hz,lz,hw,lw;
  split2(v.x,hx,lx); split2(v.y,hy,ly); split2(v.z,hz,lz); split2(v.w,hw,lw);
  dh[2*(size_t)i]   = __halves2half2(hx,hy);
  dh[2*(size_t)i+1] = __halves2half2(hz,hw);
  dl[2*(size_t)i]   = __halves2half2(lx,ly);
  dl[2*(size_t)i+1] = __halves2half2(lz,lw);
}

__global__ void __launch_bounds__(256) pack_bias(
    const float* __restrict__ bq, const float* __restrict__ bk,
    const float* __restrict__ bv, float* __restrict__ dst, int total){
  int i = blockIdx.x*256 + threadIdx.x;
  if (i >= total) return;
  int layer = i / QKVN, c = i % QKVN;
  int third = c / DD, n = c % DD;
  const float* src = (third == 0) ? bq : (third == 1) ? bk : bv;
  dst[i] = src[layer*DD + n];
}

// ======================= fp16 GEMM: TERMS=3 full, TERMS=2 drops weight-residual =======================
#define AROW 40
#define BROW 136
#define OFF_AH 0
#define OFF_AL (128*AROW)
#define OFF_BH (2*128*AROW)
#define OFF_BL (2*128*AROW + 32*BROW)
#define BUF_H  (2*128*AROW + 2*32*BROW)
#define GEMM_SMEM (2*BUF_H*2)

template<int ACT, int OUTMODE, int TERMS>
__global__ void __launch_bounds__(256) gemm_hh(
    const __half* __restrict__ Ah, const __half* __restrict__ Al,
    const __half* __restrict__ Wh, const __half* __restrict__ Wl,
    const float* __restrict__ bias, float* __restrict__ C,
    __half* __restrict__ Ch, __half* __restrict__ Cl, int M, int N, int K){
  extern __shared__ __half smh[];
  const uint32_t smb = smem_u32(smh);
  const int tid = threadIdx.x, lane = tid & 31, wid = tid >> 5;
  const int wm = wid & 1, wn = wid >> 1;
  const int g = lane >> 2, tig = lane & 3;
  const int m0 = blockIdx.y * 128, n0 = blockIdx.x * 128;

  float    acc [4][4][4] = {};
  uint32_t acc2[4][4][2] = {};
  const int a_row  = wm*64 + (lane & 7) + ((lane >> 3) & 1) * 8;
  const int a_koff = (lane & 16) ? 8 : 0;
  const int b_row  = (lane & 7) + ((lane >> 3) & 1) * 8;
  const int b_noff = wn*32 + ((lane & 16) ? 8 : 0);

  #pragma unroll
  for (int i = 0; i < 2; i++){
    int idx = tid + 256*i;
    int r = idx >> 2, c8 = (idx & 3) * 8;
    *(uint4*)&smh[OFF_AH + r*AROW + c8] = *(const uint4*)&Ah[(size_t)(m0+r)*K + c8];
    *(uint4*)&smh[OFF_AL + r*AROW + c8] = *(const uint4*)&Al[(size_t)(m0+r)*K + c8];
    int row = idx >> 4, nc = (idx & 15) * 8;
    *(uint4*)&smh[OFF_BH + row*BROW + nc] = *(const uint4*)&Wh[(size_t)row*N + n0 + nc];
    if (TERMS == 3)
      *(uint4*)&smh[OFF_BL + row*BROW + nc] = *(const uint4*)&Wl[(size_t)row*N + n0 + nc];
  }
  __syncthreads();

  const int nkt = K >> 5;
  for (int kt = 0; kt < nkt; kt++){
    uint4 rAh[2], rAl[2], rBh[2], rBl[2];
    const bool pf = (kt + 1 < nkt);
    if (pf){
      int k0 = (kt + 1) << 5;
      #pragma unroll
      for (int i = 0; i < 2; i++){
        int idx = tid + 256*i;
        int r = idx >> 2, c8 = (idx & 3) * 8;
        rAh[i] = *(const uint4*)&Ah[(size_t)(m0+r)*K + k0 + c8];
        rAl[i] = *(const uint4*)&Al[(size_t)(m0+r)*K + k0 + c8];
        int row = idx >> 4, nc = (idx & 15) * 8;
        rBh[i] = *(const uint4*)&Wh[(size_t)(k0+row)*N + n0 + nc];
        if (TERMS == 3)
          rBl[i] = *(const uint4*)&Wl[(size_t)(k0+row)*N + n0 + nc];
      }
    }
    const uint32_t bufb = smb + (uint32_t)(kt & 1) * (BUF_H * 2);

    #pragma unroll
    for (int ks = 0; ks < 2; ks++){
      uint32_t ah[4][4], al[4][4], bh[4][2], bl[4][2];
      #pragma unroll
      for (int mt = 0; mt < 4; mt++){
        uint32_t ad = bufb + (uint32_t)((a_row + mt*16)*AROW + ks*16 + a_koff) * 2;
        ldmat4(ah[mt], ad + OFF_AH*2);
        ldmat4(al[mt], ad + OFF_AL*2);
      }
      #pragma unroll
      for (int ntp = 0; ntp < 2; ntp++){
        uint32_t bd = bufb + (uint32_t)((b_row + ks*16)*BROW + b_noff + ntp*16) * 2;
        uint32_t th[4];
        ldmat4t(th, bd + OFF_BH*2);
        bh[ntp*2][0]=th[0]; bh[ntp*2][1]=th[1]; bh[ntp*2+1][0]=th[2]; bh[ntp*2+1][1]=th[3];
        if (TERMS == 3){
          uint32_t tl[4];
          ldmat4t(tl, bd + OFF_BL*2);
          bl[ntp*2][0]=tl[0]; bl[ntp*2][1]=tl[1]; bl[ntp*2+1][0]=tl[2]; bl[ntp*2+1][1]=tl[3];
        }
      }
      #pragma unroll
      for (int mt = 0; mt < 4; mt++)
        #pragma unroll
        for (int nt = 0; nt < 4; nt++){
          mma_f16(acc[mt][nt], ah[mt], bh[nt]);
          mma_f16acc(acc2[mt][nt], al[mt], bh[nt]);
          if (TERMS == 3) mma_f16acc(acc2[mt][nt], ah[mt], bl[nt]);
        }
    }

    if (pf){
      __half* dst = smh + ((kt + 1) & 1) * BUF_H;
      #pragma unroll
      for (int i = 0; i < 2; i++){
        int idx = tid + 256*i;
        int r = idx >> 2, c8 = (idx & 3) * 8;
        *(uint4*)&dst[OFF_AH + r*AROW + c8] = rAh[i];
        *(uint4*)&dst[OFF_AL + r*AROW + c8] = rAl[i];
        int row = idx >> 4, nc = (idx & 15) * 8;
        *(uint4*)&dst[OFF_BH + row*BROW + nc] = rBh[i];
        if (TERMS == 3)
          *(uint4*)&dst[OFF_BL + row*BROW + nc] = rBl[i];
      }
    }
    __syncthreads();
  }

  #pragma unroll
  for (int mt = 0; mt < 4; mt++){
    int r0 = m0 + wm*64 + mt*16 + g;
    #pragma unroll
    for (int nt = 0; nt < 4; nt++){
      int c = n0 + wn*32 + nt*8 + tig*2;
      float b0 = bias[c], b1 = bias[c+1];
      __half2 c01 = *(__half2*)&acc2[mt][nt][0];
      __half2 c23 = *(__half2*)&acc2[mt][nt][1];
      float2 v0, v1;
      v0.x = acc[mt][nt][0] + LOSCL*__low2float (c01) + b0;
      v0.y = acc[mt][nt][1] + LOSCL*__high2float(c01) + b1;
      v1.x = acc[mt][nt][2] + LOSCL*__low2float (c23) + b0;
      v1.y = acc[mt][nt][3] + LOSCL*__high2float(c23) + b1;
      if (ACT == 1){
        v0.x = 0.5f*v0.x*(1.0f + erff(v0.x*0.70710678118654752440f));
        v0.y = 0.5f*v0.y*(1.0f + erff(v0.y*0.70710678118654752440f));
        v1.x = 0.5f*v1.x*(1.0f + erff(v1.x*0.70710678118654752440f));
        v1.y = 0.5f*v1.y*(1.0f + erff(v1.y*0.70710678118654752440f));
      }
      if (OUTMODE == 0){
        *(float2*)&C[(size_t)r0*N + c]     = v0;
        *(float2*)&C[(size_t)(r0+8)*N + c] = v1;
      } else {
        __half h0,l0,h1,l1;
        split2(v0.x,h0,l0); split2(v0.y,h1,l1);
        *(__half2*)&Ch[(size_t)r0*N + c] = __halves2half2(h0,h1);
        *(__half2*)&Cl[(size_t)r0*N + c] = __halves2half2(l0,l1);
        split2(v1.x,h0,l0); split2(v1.y,h1,l1);
        *(__half2*)&Ch[(size_t)(r0+8)*N + c] = __halves2half2(h0,h1);
        *(__half2*)&Cl[(size_t)(r0+8)*N + c] = __halves2half2(l0,l1);
      }
    }
  }
}

// ======================= attention scores via mma =======================
// FULL=1 (layer 0): 3-term, fp32 S out.  FULL=0: 2-term, fp16 logits out.
#define S2_ROW 72
#define S2_AH 0
#define S2_AL (128*S2_ROW)
#define S2_BH (2*128*S2_ROW)
#define S2_BL (3*128*S2_ROW)
#define S2_SMEM (4*128*S2_ROW*2)

template<int FULL>
__global__ void __launch_bounds__(256) attn_scores_mma(
    const __half* __restrict__ qh, const __half* __restrict__ ql,
    const __half* __restrict__ kh, const __half* __restrict__ kl,
    int qs, const int* __restrict__ mix, float* __restrict__ S,
    __half* __restrict__ Slog){
  extern __shared__ __half smh[];
  const uint32_t smb = smem_u32(smh);
  const int bh = blockIdx.z, b = bh / HH, h = bh % HH;
  const int kb = mix ? mix[b] : b;
  const int i0 = blockIdx.y*128, j0 = blockIdx.x*128;
  const int tid = threadIdx.x, lane = tid & 31, wid = tid >> 5;
  const int wm = wid & 1, wn = wid >> 1;
  const int g = lane >> 2, tig = lane & 3;

  #pragma unroll
  for (int it = 0; it < 4; it++){
    int idx = tid + 256*it;
    int r = idx >> 3, c8 = (idx & 7) * 8;
    size_t qa = (size_t)(b *LL + i0 + r)*qs + h*KDIM + c8;
    size_t ka = (size_t)(kb*LL + j0 + r)*qs + h*KDIM + c8;
    *(uint4*)&smh[S2_AH + r*S2_ROW + c8] = *(const uint4*)&qh[qa];
    *(uint4*)&smh[S2_AL + r*S2_ROW + c8] = *(const uint4*)&ql[qa];
    *(uint4*)&smh[S2_BH + r*S2_ROW + c8] = *(const uint4*)&kh[ka];
    if (FULL)
      *(uint4*)&smh[S2_BL + r*S2_ROW + c8] = *(const uint4*)&kl[ka];
  }
  __syncthreads();

  float acc [4][4][4] = {};
  float acc2[4][4][4] = {};
  const int a_row  = wm*64 + (lane & 7) + ((lane >> 3) & 1) * 8;
  const int a_koff = (lane & 16) ? 8 : 0;
  const int b_nadd = wn*32 + ((lane >> 4) << 3) + (lane & 7);
  const int b_kadd = (lane & 8);

  #pragma unroll
  for (int ks = 0; ks < 4; ks++){
    uint32_t ah[4][4], al[4][4], bhf[4][2], blf[4][2];
    #pragma unroll
    for (int mt = 0; mt < 4; mt++){
      uint32_t ad = smb + (uint32_t)((a_row + mt*16)*S2_ROW + ks*16 + a_koff) * 2;
      ldmat4(ah[mt], ad + S2_AH*2);
      ldmat4(al[mt], ad + S2_AL*2);
    }
    #pragma unroll
    for (int ntp = 0; ntp < 2; ntp++){
      uint32_t bd = smb + (uint32_t)((b_nadd + ntp*16)*S2_ROW + ks*16 + b_kadd) * 2;
      uint32_t th[4];
      ldmat4(th, bd + S2_BH*2);
      bhf[ntp*2][0]=th[0]; bhf[ntp*2][1]=th[1]; bhf[ntp*2+1][0]=th[2]; bhf[ntp*2+1][1]=th[3];
      if (FULL){
        uint32_t tl[4];
        ldmat4(tl, bd + S2_BL*2);
        blf[ntp*2][0]=tl[0]; blf[ntp*2][1]=tl[1]; blf[ntp*2+1][0]=tl[2]; blf[ntp*2+1][1]=tl[3];
      }
    }
    #pragma unroll
    for (int mt = 0; mt < 4; mt++)
      #pragma unroll
      for (int nt = 0; nt < 4; nt++){
        mma_f16(acc [mt][nt], ah[mt], bhf[nt]);
        mma_f16(acc2[mt][nt], al[mt], bhf[nt]);
        if (FULL) mma_f16(acc2[mt][nt], ah[mt], blf[nt]);
      }
  }

  #pragma unroll
  for (int mt = 0; mt < 4; mt++){
    int r0 = i0 + wm*64 + mt*16 + g;
    #pragma unroll
    for (int nt = 0; nt < 4; nt++){
      int c = j0 + wn*32 + nt*8 + tig*2;
      float2 v0, v1;
      v0.x = (acc[mt][nt][0] + LOSCL*acc2[mt][nt][0]) * 0.125f;
      v0.y = (acc[mt][nt][1] + LOSCL*acc2[mt][nt][1]) * 0.125f;
      v1.x = (acc[mt][nt][2] + LOSCL*acc2[mt][nt][2]) * 0.125f;
      v1.y = (acc[mt][nt][3] + LOSCL*acc2[mt][nt][3]) * 0.125f;
      if (FULL){
        float* sbase = S + (size_t)bh*LL*LL;
        *(float2*)&sbase[(size_t)r0*LL + c]     = v0;
        *(float2*)&sbase[(size_t)(r0+8)*LL + c] = v1;
      } else {
        __half* lbase = Slog + (size_t)bh*LL*LL;
        *(__half2*)&lbase[(size_t)r0*LL + c]     = __halves2half2(__float2half_rn(v0.x), __float2half_rn(v0.y));
        *(__half2*)&lbase[(size_t)(r0+8)*LL + c] = __halves2half2(__float2half_rn(v1.x), __float2half_rn(v1.y));
      }
    }
  }
}

// ======================= O = P @ V via mma, P single fp16 (exact 2-term) =======================
#define V_AROW 40
#define V_BROW 72
#define V_A  0
#define V_BH (128*V_AROW)
#define V_BL (128*V_AROW + 32*V_BROW)
#define V_BUF (128*V_AROW + 2*32*V_BROW)
#define V_SMEM (2*V_BUF*2)

__global__ void __launch_bounds__(256) attn_av_mma(
    const __half* __restrict__ Sp,
    const __half* __restrict__ vh, const __half* __restrict__ vl, int vs,
    __half* __restrict__ oh, __half* __restrict__ ol){
  extern __shared__ __half smh[];
  const uint32_t smb = smem_u32(smh);
  const int bh = blockIdx.y, b = bh / HH, h = bh % HH;
  const int i0 = blockIdx.x*128;
  const int tid = threadIdx.x, lane = tid & 31, wid = tid >> 5;
  const int wm = wid & 3, wn = wid >> 2;
  const int g = lane >> 2, tig = lane & 3;
  const __half* spb = Sp + (size_t)bh*LL*LL;

  float acc [2][4][4] = {};
  float acc2[2][4][4] = {};
  const int a_row  = wm*32 + (lane & 7) + ((lane >> 3) & 1) * 8;
  const int a_koff = (lane & 16) ? 8 : 0;
  const int b_row  = (lane & 7) + ((lane >> 3) & 1) * 8;
  const int b_noff = wn*32 + ((lane & 16) ? 8 : 0);

  #pragma unroll
  for (int i = 0; i < 2; i++){
    int idx = tid + 256*i;
    int r = idx >> 2, c8 = (idx & 3) * 8;
    *(uint4*)&smh[V_A + r*V_AROW + c8] = *(const uint4*)&spb[(size_t)(i0 + r)*LL + c8];
  }
  {
    int r = tid >> 3, c8 = (tid & 7) * 8;
    size_t va = (size_t)(b*LL + r)*vs + h*KDIM + c8;
    *(uint4*)&smh[V_BH + r*V_BROW + c8] = *(const uint4*)&vh[va];
    *(uint4*)&smh[V_BL + r*V_BROW + c8] = *(const uint4*)&vl[va];
  }
  __syncthreads();

  for (int kt = 0; kt < 16; kt++){
    uint4 rA[2], rBh, rBl;
    const bool pf = (kt + 1 < 16);
    if (pf){
      int k0 = (kt + 1) << 5;
      #pragma unroll
      for (int i = 0; i < 2; i++){
        int idx = tid + 256*i;
        int r = idx >> 2, c8 = (idx & 3) * 8;
        rA[i] = *(const uint4*)&spb[(size_t)(i0 + r)*LL + k0 + c8];
      }
      int r = tid >> 3, c8 = (tid & 7) * 8;
      size_t va = (size_t)(b*LL + k0 + r)*vs + h*KDIM + c8;
      rBh = *(const uint4*)&vh[va];
      rBl = *(const uint4*)&vl[va];
    }
    const uint32_t bufb = smb + (uint32_t)(kt & 1) * (V_BUF * 2);

    #pragma unroll
    for (int ks = 0; ks < 2; ks++){
      uint32_t ah[2][4], bhf[4][2], blf[4][2];
      #pragma unroll
      for (int mt = 0; mt < 2; mt++){
        uint32_t ad = bufb + (uint32_t)((a_row + mt*16)*V_AROW + ks*16 + a_koff) * 2;
        ldmat4(ah[mt], ad + V_A*2);
      }
      #pragma unroll
      for (int ntp = 0; ntp < 2; ntp++){
        uint32_t bd = bufb + (uint32_t)((b_row + ks*16)*V_BROW + b_noff + ntp*16) * 2;
        uint32_t th[4], tl[4];
        ldmat4t(th, bd + V_BH*2);
        ldmat4t(tl, bd + V_BL*2);
        bhf[ntp*2][0]=th[0]; bhf[ntp*2][1]=th[1]; bhf[ntp*2+1][0]=th[2]; bhf[ntp*2+1][1]=th[3];
        blf[ntp*2][0]=tl[0]; blf[ntp*2][1]=tl[1]; blf[ntp*2+1][0]=tl[2]; blf[ntp*2+1][1]=tl[3];
      }
      #pragma unroll
      for (int mt = 0; mt < 2; mt++)
        #pragma unroll
        for (int nt = 0; nt < 4; nt++){
          mma_f16(acc [mt][nt], ah[mt], bhf[nt]);
          mma_f16(acc2[mt][nt], ah[mt], blf[nt]);
        }
    }

    if (pf){
      __half* dst = smh + ((kt + 1) & 1) * V_BUF;
      #pragma unroll
      for (int i = 0; i < 2; i++){
        int idx = tid + 256*i;
        int r = idx >> 2, c8 = (idx & 3) * 8;
        *(uint4*)&dst[V_A + r*V_AROW + c8] = rA[i];
      }
      int r = tid >> 3, c8 = (tid & 7) * 8;
      *(uint4*)&dst[V_BH + r*V_BROW + c8] = rBh;
      *(uint4*)&dst[V_BL + r*V_BROW + c8] = rBl;
    }
    __syncthreads();
  }

  #pragma unroll
  for (int mt = 0; mt < 2; mt++){
    int r0 = i0 + wm*32 + mt*16 + g;
    #pragma unroll
    for (int nt = 0; nt < 4; nt++){
      int c = wn*32 + nt*8 + tig*2;
      float2 v0, v1;
      v0.x = acc[mt][nt][0] + LOSCL*acc2[mt][nt][0];
      v0.y = acc[mt][nt][1] + LOSCL*acc2[mt][nt][1];
      v1.x = acc[mt][nt][2] + LOSCL*acc2[mt][nt][2];
      v1.y = acc[mt][nt][3] + LOSCL*acc2[mt][nt][3];
      size_t o0 = (size_t)(b*LL + r0)*DD + h*KDIM + c;
      size_t o1 = (size_t)(b*LL + r0 + 8)*DD + h*KDIM + c;
      __half h0,l0,h1,l1;
      split2(v0.x,h0,l0); split2(v0.y,h1,l1);
      *(__half2*)&oh[o0] = __halves2half2(h0,h1);
      *(__half2*)&ol[o0] = __halves2half2(l0,l1);
      split2(v1.x,h0,l0); split2(v1.y,h1,l1);
      *(__half2*)&oh[o1] = __halves2half2(h0,h1);
      *(__half2*)&ol[o1] = __halves2half2(l0,l1);
    }
  }
}

// ---------------- reductions ----------------
__device__ __forceinline__ float warpSum(float v){
  #pragma unroll
  for (int o=16;o;o>>=1) v += __shfl_xor_sync(0xffffffffu, v, o);
  return v;
}
__device__ __forceinline__ float warpMax(float v){
  #pragma unroll
  for (int o=16;o;o>>=1) v = fmaxf(v, __shfl_xor_sync(0xffffffffu, v, o));
  return v;
}
template<int NWARP>
__device__ __forceinline__ float blockSum(float v, float* sh){
  int lane = threadIdx.x & 31, w = threadIdx.x >> 5;
  v = warpSum(v);
  if (lane == 0) sh[w] = v;
  __syncthreads();
  float r = (lane < NWARP) ? sh[lane] : 0.f;
  r = warpSum(r);
  __syncthreads();
  return r;
}
template<int NWARP>
__device__ __forceinline__ float blockMax(float v, float* sh){
  int lane = threadIdx.x & 31, w = threadIdx.x >> 5;
  v = warpMax(v);
  if (lane == 0) sh[w] = v;
  __syncthreads();
  float r = (lane < NWARP) ? sh[lane] : -INFINITY;
  r = warpMax(r);
  __syncthreads();
  return r;
}

// ---------------- masked softmax, warp-per-row ----------------
template<int FULL>
__global__ void __launch_bounds__(512) softmax512(float* __restrict__ S,
    const __half* __restrict__ Slog, __half* __restrict__ Sp,
    const float* __restrict__ amask, const int* __restrict__ mix){
  const int row = blockIdx.x*16 + (threadIdx.x >> 5);
  const int lane = threadIdx.x & 31;
  const int bh = row >> 9;
  const int b  = bh / HH;
  const int kb = mix ? mix[b] : b;
  float* sr = S + (size_t)row*LL;
  const __half* lr = Slog + (size_t)row*LL;
  __half* spr = Sp + (size_t)row*LL;
  const float* mr = amask + (size_t)kb*LL;

  float4 v4[4], m4[4];
  float mx = -INFINITY;
  #pragma unroll
  for (int c = 0; c < 4; c++){
    int j = lane*4 + c*128;
    if (FULL){
      v4[c] = *(const float4*)&sr[j];
    } else {
      uint2 hv = *(const uint2*)&lr[j];
      const __half* ph = (const __half*)&hv;
      v4[c].x = __half2float(ph[0]); v4[c].y = __half2float(ph[1]);
      v4[c].z = __half2float(ph[2]); v4[c].w = __half2float(ph[3]);
    }
    m4[c] = *(const float4*)&mr[j];
    v4[c].x *= m4[c].x; v4[c].y *= m4[c].y; v4[c].z *= m4[c].z; v4[c].w *= m4[c].w;
    mx = fmaxf(mx, fmaxf(fmaxf(v4[c].x, v4[c].y), fmaxf(v4[c].z, v4[c].w)));
  }
  mx = warpMax(mx);
  float s = 0.f;
  #pragma unroll
  for (int c = 0; c < 4; c++){
    v4[c].x = expf(v4[c].x - mx)*m4[c].x;
    v4[c].y = expf(v4[c].y - mx)*m4[c].y;
    v4[c].z = expf(v4[c].z - mx)*m4[c].z;
    v4[c].w = expf(v4[c].w - mx)*m4[c].w;
    s += v4[c].x + v4[c].y + v4[c].z + v4[c].w;
  }
  s = warpSum(s);
  if (s == 0.f) s = 1.f;
  float inv = 1.f/s;
  #pragma unroll
  for (int c = 0; c < 4; c++){
    int j = lane*4 + c*128;
    float4 p;
    p.x = v4[c].x*inv; p.y = v4[c].y*inv; p.z = v4[c].z*inv; p.w = v4[c].w*inv;
    if (FULL) *(float4*)&sr[j] = p;
    __half h4[4];
    h4[0] = __float2half_rn(p.x); h4[1] = __float2half_rn(p.y);
    h4[2] = __float2half_rn(p.z); h4[3] = __float2half_rn(p.w);
    *(uint2*)&spr[j] = *(uint2*)h4;
  }
}

// ---------------- cross-sim argmax ----------------
__global__ void __launch_bounds__(256) cross_argmax(const float* __restrict__ S,
    int* __restrict__ pos){
  const int i = blockIdx.x, b = blockIdx.y;
  if (i == 0 || i == LL-1){
    if (threadIdx.x == 0) pos[b*LL + i] = i;
    return;
  }
  __shared__ float sval[256];
  __shared__ int   sidx[256];
  float best = -1.f; int bestj = 0;
  for (int j = threadIdx.x; j < LL; j += 256){
    if (j < 1 || j > LL-2) continue;
    float cs = -INFINITY;
    #pragma unroll
    for (int h=0; h<HH; h++)
      cs = fmaxf(cs, S[((size_t)(b*HH+h)*LL + i)*LL + j]);
    if (cs > best || (cs == best && j > bestj)){ best = cs; bestj = j; }
  }
  sval[threadIdx.x]=best; sidx[threadIdx.x]=bestj;
  __syncthreads();
  for (int s=128; s; s>>=1){
    if (threadIdx.x < s){
      float v2 = sval[threadIdx.x+s]; int j2 = sidx[threadIdx.x+s];
      if (v2 > sval[threadIdx.x] || (v2 == sval[threadIdx.x] && j2 > sidx[threadIdx.x])){
        sval[threadIdx.x]=v2; sidx[threadIdx.x]=j2;
      }
    }
    __syncthreads();
  }
  if (threadIdx.x == 0) pos[b*LL + i] = sidx[0];
}

// ---------------- mixup apply ----------------
__global__ void __launch_bounds__(256) mixup_apply(const float* __restrict__ h,
    const int* __restrict__ mix, const int* __restrict__ pos,
    const float* __restrict__ alphap, float* __restrict__ outh){
  const int t = blockIdx.x, b = t / LL;
  const float a = *alphap;
  const int mb = mix[b], p = pos[t];
  const float* cur = h + (size_t)t*DD;
  const float* src = h + (size_t)(mb*LL + p)*DD;
  float* dst = outh + (size_t)t*DD;
  for (int d = threadIdx.x; d < DD; d += 256)
    dst[d] = a*cur[d] + (1.f-a)*src[d];
}

__global__ void __launch_bounds__(256) copy_split(const float* __restrict__ src,
    float* __restrict__ dst, __half* __restrict__ dh, __half* __restrict__ dl, int n){
  int i = blockIdx.x*256 + threadIdx.x;
  if (i < n){
    float x = src[i];
    dst[i] = x;
    __half hi, lo; split2(x, hi, lo);
    dh[i] = hi; dl[i] = lo;
  }
}

// ---------------- embedding + LN ----------------
__global__ void __launch_bounds__(256) embed_ln(const int* __restrict__ ids,
    const float* __restrict__ we, const float* __restrict__ pe, const float* __restrict__ te,
    const float* __restrict__ w, const float* __restrict__ bprm,
    float* __restrict__ h, __half* __restrict__ hh, __half* __restrict__ hl){
  const int t = blockIdx.x, l = t % LL;
  __shared__ float red[8];
  const int id = ids[t];
  float xs[3]; float s = 0.f;
  #pragma unroll
  for (int r=0;r<3;r++){
    int d = threadIdx.x + 256*r;
    float x = we[(size_t)id*DD + d] + pe[(size_t)l*DD + d] + te[d];
    xs[r]=x; s += x;
  }
  float mu = blockSum<8>(s, red) * (1.f/DD);
  float vs = 0.f;
  #pragma unroll
  for (int r=0;r<3;r++){ float c = xs[r]-mu; vs += c*c; }
  float var = blockSum<8>(vs, red) * (1.f/DD);
  float rstd = rsqrtf(var + 1e-12f);
  #pragma unroll
  for (int r=0;r<3;r++){
    int d = threadIdx.x + 256*r;
    float y = (xs[r]-mu)*rstd*w[d] + bprm[d];
    h[(size_t)t*DD + d] = y;
    __half hi, lo; split2(y, hi, lo);
    hh[(size_t)t*DD + d] = hi; hl[(size_t)t*DD + d] = lo;
  }
}

// ---------------- h = LN(hin + res) ----------------
__global__ void __launch_bounds__(256) add_ln(const float* __restrict__ hin,
    const float* __restrict__ res, const float* __restrict__ w,
    const float* __restrict__ bprm, float* __restrict__ hout,
    __half* __restrict__ hh, __half* __restrict__ hl){
  const int t = blockIdx.x;
  __shared__ float red[8];
  float xs[3]; float s = 0.f;
  #pragma unroll
  for (int r=0;r<3;r++){
    int d = threadIdx.x + 256*r;
    float x = hin[(size_t)t*DD + d] + res[(size_t)t*DD + d];
    xs[r]=x; s += x;
  }
  float mu = blockSum<8>(s, red) * (1.f/DD);
  float vs = 0.f;
  #pragma unroll
  for (int r=0;r<3;r++){ float c = xs[r]-mu; vs += c*c; }
  float var = blockSum<8>(vs, red) * (1.f/DD);
  float rstd = rsqrtf(var + 1e-12f);
  #pragma unroll
  for (int r=0;r<3;r++){
    int d = threadIdx.x + 256*r;
    float y = (xs[r]-mu)*rstd*w[d] + bprm[d];
    hout[(size_t)t*DD + d] = y;
    __half hi, lo; split2(y, hi, lo);
    hh[(size_t)t*DD + d] = hi; hl[(size_t)t*DD + d] = lo;
  }
}

// ---------------- mean pool (two stage) ----------------
__global__ void __launch_bounds__(256) pool_part(const float* __restrict__ h,
    float* __restrict__ part){
  const int b = blockIdx.x, chunk = blockIdx.y;
  float acc[3] = {0.f,0.f,0.f};
  for (int l = chunk*32; l < chunk*32 + 32; l++){
    const float* row = h + (size_t)(b*LL + l)*DD;
    #pragma unroll
    for (int r=0;r<3;r++) acc[r] += row[threadIdx.x + 256*r];
  }
  #pragma unroll
  for (int r=0;r<3;r++)
    part[((size_t)b*16 + chunk)*DD + threadIdx.x + 256*r] = acc[r];
}
__global__ void __launch_bounds__(256) pool_final(const float* __restrict__ part,
    float* __restrict__ p){
  const int b = blockIdx.x;
  float acc[3] = {0.f,0.f,0.f};
  for (int c = 0; c < 16; c++){
    #pragma unroll
    for (int r=0;r<3;r++)
      acc[r] += part[((size_t)b*16 + c)*DD + threadIdx.x + 256*r];
  }
  #pragma unroll
  for (int r=0;r<3;r++)
    p[(size_t)b*DD + threadIdx.x + 256*r] = acc[r]*(1.f/LL);
}

// ---------------- classifier head ----------------
__global__ void __launch_bounds__(128) head_kernel(const float* __restrict__ p,
    const float* __restrict__ c1w, const float* __restrict__ c1b,
    const float* __restrict__ c2w, const float* __restrict__ c2b,
    float* __restrict__ out){
  const int b = blockIdx.x;
  __shared__ float ps[DD];
  __shared__ float c1s[128];
  for (int d = threadIdx.x; d < DD; d += 128) ps[d] = p[(size_t)b*DD + d];
  __syncthreads();
  const int t = threadIdx.x;
  float s = c1b[t];
  for (int d = 0; d < DD; d++) s += ps[d]*c1w[(size_t)d*128 + t];
  c1s[t] = tanhf(s);
  __syncthreads();
  if (t < NCLS){
    float o = c2b[t];
    #pragma unroll
    for (int j=0;j<128;j++) o += c1s[j]*c2w[j*NCLS + t];
    out[b*NCLS + t] = o;
  }
}

// ---------------- launcher ----------------
extern "C" void kernel_launch(void* const* d_in, const int* in_sizes, int n_in,
                              void* d_out, int out_size){
  const int*   ids   = (const int*)  d_in[0];
  const float* amask = (const float*)d_in[1];
  const int*   mix   = (const int*)  d_in[2];
  const float* alpha = (const float*)d_in[6];
  const float* we    = (const float*)d_in[7];
  const float* pe    = (const float*)d_in[8];
  const float* te    = (const float*)d_in[9];
  const float* elnw  = (const float*)d_in[10];
  const float* elnb  = (const float*)d_in[11];
  const float* Wq = (const float*)d_in[12]; const float* bq = (const float*)d_in[13];
  const float* Wk = (const float*)d_in[14]; const float* bk = (const float*)d_in[15];
  const float* Wv = (const float*)d_in[16]; const float* bv = (const float*)d_in[17];
  const float* Wo = (const float*)d_in[18]; const float* bo = (const float*)d_in[19];
  const float* l1w = (const float*)d_in[20]; const float* l1b = (const float*)d_in[21];
  const float* Wf1 = (const float*)d_in[22]; const float* bf1 = (const float*)d_in[23];
  const float* Wf2 = (const float*)d_in[24]; const float* bf2 = (const float*)d_in[25];
  const float* l2w = (const float*)d_in[26]; const float* l2b = (const float*)d_in[27];
  const float* c1w = (const float*)d_in[28]; const float* c1b = (const float*)d_in[29];
  const float* c2w = (const float*)d_in[30]; const float* c2b = (const float*)d_in[31];
  float* out = (float*)d_out;

  float *h,*t2,*sc,*pl,*part,*bqkv; int* mpos;
  cudaGetSymbolAddress((void**)&h,    g_h);
  cudaGetSymbolAddress((void**)&t2,   g_t2);
  cudaGetSymbolAddress((void**)&sc,   g_scores);
  cudaGetSymbolAddress((void**)&pl,   g_pooled);
  cudaGetSymbolAddress((void**)&part, g_part);
  cudaGetSymbolAddress((void**)&mpos, g_mixpos);
  cudaGetSymbolAddress((void**)&bqkv, g_bqkv);

  __half *hh,*hl,*qkvh,*qkvl,*oh,*ol,*t1h,*t1l,*Sp,*Slog;
  cudaGetSymbolAddress((void**)&hh,   g_hh);   cudaGetSymbolAddress((void**)&hl,   g_hl);
  cudaGetSymbolAddress((void**)&qkvh, g_qkvh); cudaGetSymbolAddress((void**)&qkvl, g_qkvl);
  cudaGetSymbolAddress((void**)&oh,   g_oh);   cudaGetSymbolAddress((void**)&ol,   g_ol);
  cudaGetSymbolAddress((void**)&t1h,  g_t1h);  cudaGetSymbolAddress((void**)&t1l,  g_t1l);
  cudaGetSymbolAddress((void**)&Sp,   g_Sp);   cudaGetSymbolAddress((void**)&Slog, g_Slog);

  __half *Wqkvh,*Wqkvl,*Woh,*Wol,*Wf1h,*Wf1l,*Wf2h,*Wf2l;
  cudaGetSymbolAddress((void**)&Wqkvh, g_Wqkvh); cudaGetSymbolAddress((void**)&Wqkvl, g_Wqkvl);
  cudaGetSymbolAddress((void**)&Woh,   g_Woh);   cudaGetSymbolAddress((void**)&Wol,   g_Wol);
  cudaGetSymbolAddress((void**)&Wf1h,  g_Wf1h);  cudaGetSymbolAddress((void**)&Wf1l,  g_Wf1l);
  cudaGetSymbolAddress((void**)&Wf2h,  g_Wf2h);  cudaGetSymbolAddress((void**)&Wf2l,  g_Wf2l);

  static int attrset = 0;
  if (!attrset){
    cudaFuncSetAttribute(gemm_hh<0,0,2>, cudaFuncAttributeMaxDynamicSharedMemorySize, GEMM_SMEM);
    cudaFuncSetAttribute(gemm_hh<1,1,2>, cudaFuncAttributeMaxDynamicSharedMemorySize, GEMM_SMEM);
    cudaFuncSetAttribute(gemm_hh<0,1,3>, cudaFuncAttributeMaxDynamicSharedMemorySize, GEMM_SMEM);
    cudaFuncSetAttribute(attn_scores_mma<0>, cudaFuncAttributeMaxDynamicSharedMemorySize, S2_SMEM);
    cudaFuncSetAttribute(attn_scores_mma<1>, cudaFuncAttributeMaxDynamicSharedMemorySize, S2_SMEM);
    cudaFuncSetAttribute(attn_av_mma,        cudaFuncAttributeMaxDynamicSharedMemorySize, V_SMEM);
    attrset = 1;
  }

  // prep
  {
    int tq4 = NLAY*DD*QKVN/4;
    pack_qkv<<<(tq4+255)/256, 256>>>((const float4*)Wq, (const float4*)Wk,
                                     (const float4*)Wv, (__half2*)Wqkvh, (__half2*)Wqkvl, tq4);
    pack_bias<<<(NLAY*QKVN+255)/256, 256>>>(bq, bk, bv, bqkv, NLAY*QKVN);
  }
  embed_ln<<<NTOK,256>>>(ids, we, pe, te, elnw, elnb, h, hh, hl);

  bool wprep = false;
  for (int layer = 0; layer < NLAY; layer++){
    const size_t od3 = (size_t)layer*DD*QKVN;
    const size_t od  = (size_t)layer*DD*DD;
    const size_t of  = (size_t)layer*DD*FFD;
    const float* bqkv_l = bqkv + (size_t)layer*QKVN;
    const float* bo_l   = bo   + (size_t)layer*DD;
    const float* bf1_l  = bf1  + (size_t)layer*FFD;
    const float* bf2_l  = bf2  + (size_t)layer*DD;
    dim3 gdd(DD/128, NTOK/128), gdf(FFD/128, NTOK/128), gqkv(QKVN/128, NTOK/128);

    if (layer == 0){
      gemm_hh<0,1,3><<<dim3(12, NTOK/128), 256, GEMM_SMEM>>>(hh, hl, Wqkvh+od3, Wqkvl+od3,
          bqkv_l, nullptr, qkvh, qkvl, NTOK, QKVN, DD);
      if (!wprep){
        int n4s = NLAY*DD*DD/4;
        split_w<<<(n4s+255)/256, 256>>>((const float4*)Wo, (__half2*)Woh, (__half2*)Wol, n4s);
        int n4f = NLAY*DD*FFD/4;
        split_w2<<<dim3((n4f+255)/256, 2), 256>>>((const float4*)Wf1, (__half2*)Wf1h, (__half2*)Wf1l,
                                                  (const float4*)Wf2, (__half2*)Wf2h, (__half2*)Wf2l, n4f);
        wprep = true;
      }
      attn_scores_mma<1><<<dim3(LL/128, LL/128, BB*HH), 256, S2_SMEM>>>(
          qkvh, qkvl, qkvh+DD, qkvl+DD, QKVN, mix, sc, nullptr);
      softmax512<1><<<BB*HH*LL/16, 512>>>(sc, nullptr, Sp, amask, mix);
      cross_argmax<<<dim3(LL, BB), 256>>>(sc, mpos);
      mixup_apply<<<NTOK, 256>>>(h, mix, mpos, alpha, t2);
      copy_split<<<(NTOK*DD + 255)/256, 256>>>(t2, h, hh, hl, NTOK*DD);
    }

    gemm_hh<0,1,3><<<gqkv, 256, GEMM_SMEM>>>(hh, hl, Wqkvh+od3, Wqkvl+od3,
        bqkv_l, nullptr, qkvh, qkvl, NTOK, QKVN, DD);

    attn_scores_mma<0><<<dim3(LL/128, LL/128, BB*HH), 256, S2_SMEM>>>(
        qkvh, qkvl, qkvh+DD, qkvl+DD, QKVN, nullptr, nullptr, Slog);
    softmax512<0><<<BB*HH*LL/16, 512>>>(nullptr, Slog, Sp, amask, nullptr);
    attn_av_mma<<<dim3(LL/128, BB*HH), 256, V_SMEM>>>(Sp, qkvh+2*DD, qkvl+2*DD, QKVN, oh, ol);

    gemm_hh<0,0,2><<<gdd, 256, GEMM_SMEM>>>(oh, ol, Woh+od, Wol+od, bo_l, t2,
        nullptr, nullptr, NTOK, DD, DD);
    add_ln<<<NTOK, 256>>>(h, t2, l1w + (size_t)layer*DD, l1b + (size_t)layer*DD, h, hh, hl);

    gemm_hh<1,1,2><<<gdf, 256, GEMM_SMEM>>>(hh, hl, Wf1h+of, Wf1l+of, bf1_l,
        nullptr, t1h, t1l, NTOK, FFD, DD);
    gemm_hh<0,0,2><<<gdd, 256, GEMM_SMEM>>>(t1h, t1l, Wf2h+of, Wf2l+of, bf2_l, t2,
        nullptr, nullptr, NTOK, DD, FFD);
    add_ln<<<NTOK, 256>>>(h, t2, l2w + (size_t)layer*DD, l2b + (size_t)layer*DD, h, hh, hl);
  }

  pool_part<<<dim3(BB,16), 256>>>(h, part);
  pool_final<<<BB, 256>>>(part, pl);
  head_kernel<<<BB, 128>>>(pl, c1w, c1b, c2w, c2b, out);
}

// round 17
// speedup vs baseline: 1.5102x; 1.5102x over previous
#include <cuda_runtime.h>
#include <cuda_fp16.h>
#include <math.h>
#include <stdint.h>

#define BB   16
#define LL   512
#define DD   768
#define HH   12
#define KDIM 64
#define FFD  3072
#define NLAY 12
#define NCLS 4
#define NTOK (BB*LL)   // 8192
#define QKVN 2304

// ---------------- scratch ----------------
__device__ float g_h [NTOK*DD];
__device__ float g_t2[NTOK*DD];
__device__ float g_scores[(size_t)BB*HH*LL*LL];     // fp32 S (layer-0 only)
__device__ int   g_mixpos[NTOK];
__device__ float g_pooled[BB*DD];
__device__ float g_part[BB*16*DD];

__device__ __half g_hh[NTOK*DD],  g_hl[NTOK*DD];
__device__ __half g_qkvh[(size_t)NTOK*QKVN], g_qkvl[(size_t)NTOK*QKVN];
__device__ __half g_oh[NTOK*DD],  g_ol[NTOK*DD];
__device__ __half g_t1h[(size_t)NTOK*FFD], g_t1l[(size_t)NTOK*FFD];
__device__ __half g_Sp[(size_t)BB*HH*LL*LL];        // softmax probs (fp16)
__device__ __half g_Slog[(size_t)BB*HH*LL*LL];      // fp16 logits (standard layers)

// packed / split weights
__device__ __half g_Wqkvh[(size_t)NLAY*DD*QKVN], g_Wqkvl[(size_t)NLAY*DD*QKVN];
__device__ float  g_bqkv[NLAY*QKVN];
__device__ __half g_Woh[NLAY*DD*DD],  g_Wol[NLAY*DD*DD];
__device__ __half g_Wf1h[(size_t)NLAY*DD*FFD], g_Wf1l[(size_t)NLAY*DD*FFD];
__device__ __half g_Wf2h[(size_t)NLAY*DD*FFD], g_Wf2l[(size_t)NLAY*DD*FFD];

__device__ __forceinline__ uint32_t smem_u32(const void* p){
  uint32_t a;
  asm("{ .reg .u64 t; cvta.to.shared.u64 t, %1; cvt.u32.u64 %0, t; }" : "=r"(a) : "l"(p));
  return a;
}
__device__ __forceinline__ void mma_f16(float* d, const uint32_t* a, const uint32_t* b){
  asm volatile(
    "mma.sync.aligned.m16n8k16.row.col.f32.f16.f16.f32 "
    "{%0,%1,%2,%3},{%4,%5,%6,%7},{%8,%9},{%0,%1,%2,%3};"
    : "+f"(d[0]), "+f"(d[1]), "+f"(d[2]), "+f"(d[3])
    : "r"(a[0]), "r"(a[1]), "r"(a[2]), "r"(a[3]), "r"(b[0]), "r"(b[1]));
}
__device__ __forceinline__ void mma_f16acc(uint32_t* d, const uint32_t* a, const uint32_t* b){
  asm volatile(
    "mma.sync.aligned.m16n8k16.row.col.f16.f16.f16.f16 "
    "{%0,%1},{%2,%3,%4,%5},{%6,%7},{%0,%1};"
    : "+r"(d[0]), "+r"(d[1])
    : "r"(a[0]), "r"(a[1]), "r"(a[2]), "r"(a[3]), "r"(b[0]), "r"(b[1]));
}
__device__ __forceinline__ void ldmat4(uint32_t* r, uint32_t addr){
  asm volatile("ldmatrix.sync.aligned.m8n8.x4.shared.b16 {%0,%1,%2,%3}, [%4];"
    : "=r"(r[0]), "=r"(r[1]), "=r"(r[2]), "=r"(r[3]) : "r"(addr));
}
__device__ __forceinline__ void ldmat4t(uint32_t* r, uint32_t addr){
  asm volatile("ldmatrix.sync.aligned.m8n8.x4.trans.shared.b16 {%0,%1,%2,%3}, [%4];"
    : "=r"(r[0]), "=r"(r[1]), "=r"(r[2]), "=r"(r[3]) : "r"(addr));
}
__device__ __forceinline__ void split2(float x, __half& h, __half& l){
  h = __float2half_rn(x);
  l = __float2half_rn((x - __half2float(h)) * 4096.0f);
}
#define LOSCL (1.0f/4096.0f)

// ---------------- weight prep kernels ----------------
__global__ void __launch_bounds__(256) split_w(const float4* __restrict__ src,
    __half2* __restrict__ hi, __half2* __restrict__ lo, int n4){
  int i = blockIdx.x*256 + threadIdx.x;
  if (i >= n4) return;
  float4 v = src[i];
  __half hx,lx,hy,ly,hz,lz,hw,lw;
  split2(v.x,hx,lx); split2(v.y,hy,ly); split2(v.z,hz,lz); split2(v.w,hw,lw);
  hi[2*(size_t)i]   = __halves2half2(hx,hy);
  hi[2*(size_t)i+1] = __halves2half2(hz,hw);
  lo[2*(size_t)i]   = __halves2half2(lx,ly);
  lo[2*(size_t)i+1] = __halves2half2(lz,lw);
}

__global__ void __launch_bounds__(256) split_w2(
    const float4* __restrict__ s0, __half2* __restrict__ h0, __half2* __restrict__ l0,
    const float4* __restrict__ s1, __half2* __restrict__ h1, __half2* __restrict__ l1,
    int n4){
  int i = blockIdx.x*256 + threadIdx.x;
  if (i >= n4) return;
  const float4* s = blockIdx.y ? s1 : s0;
  __half2* hh = blockIdx.y ? h1 : h0;
  __half2* ll = blockIdx.y ? l1 : l0;
  float4 v = s[i];
  __half hx,lx,hy,ly,hz,lz,hw,lw;
  split2(v.x,hx,lx); split2(v.y,hy,ly); split2(v.z,hz,lz); split2(v.w,hw,lw);
  hh[2*(size_t)i]   = __halves2half2(hx,hy);
  hh[2*(size_t)i+1] = __halves2half2(hz,hw);
  ll[2*(size_t)i]   = __halves2half2(lx,ly);
  ll[2*(size_t)i+1] = __halves2half2(lz,lw);
}

__global__ void __launch_bounds__(256) pack_qkv(
    const float4* __restrict__ Wq, const float4* __restrict__ Wk,
    const float4* __restrict__ Wv,
    __half2* __restrict__ dh, __half2* __restrict__ dl, int total4){
  int i = blockIdx.x*256 + threadIdx.x;
  if (i >= total4) return;
  int row = i / 576, cw = i % 576;
  int third = cw / 192, c4 = cw % 192;
  const float4* src = (third == 0) ? Wq : (third == 1) ? Wk : Wv;
  float4 v = src[(size_t)row*192 + c4];
  __half hx,lx,hy,ly,hz,lz,hw,lw;
  split2(v.x,hx,lx); split2(v.y,hy,ly); split2(v.z,hz,lz); split2(v.w,hw,lw);
  dh[2*(size_t)i]   = __halves2half2(hx,hy);
  dh[2*(size_t)i+1] = __halves2half2(hz,hw);
  dl[2*(size_t)i]   = __halves2half2(lx,ly);
  dl[2*(size_t)i+1] = __halves2half2(lz,lw);
}

__global__ void __launch_bounds__(256) pack_bias(
    const float* __restrict__ bq, const float* __restrict__ bk,
    const float* __restrict__ bv, float* __restrict__ dst, int total){
  int i = blockIdx.x*256 + threadIdx.x;
  if (i >= total) return;
  int layer = i / QKVN, c = i % QKVN;
  int third = c / DD, n = c % DD;
  const float* src = (third == 0) ? bq : (third == 1) ? bk : bv;
  dst[i] = src[layer*DD + n];
}

// ======================= fp16 GEMM: TERMS=3 full, TERMS=2 drops weight-residual =======================
#define AROW 40
#define BROW 136
#define OFF_AH 0
#define OFF_AL (128*AROW)
#define OFF_BH (2*128*AROW)
#define OFF_BL (2*128*AROW + 32*BROW)
#define BUF_H  (2*128*AROW + 2*32*BROW)
#define GEMM_SMEM (2*BUF_H*2)

template<int ACT, int OUTMODE, int TERMS>
__global__ void __launch_bounds__(256) gemm_hh(
    const __half* __restrict__ Ah, const __half* __restrict__ Al,
    const __half* __restrict__ Wh, const __half* __restrict__ Wl,
    const float* __restrict__ bias, float* __restrict__ C,
    __half* __restrict__ Ch, __half* __restrict__ Cl, int M, int N, int K){
  extern __shared__ __half smh[];
  const uint32_t smb = smem_u32(smh);
  const int tid = threadIdx.x, lane = tid & 31, wid = tid >> 5;
  const int wm = wid & 1, wn = wid >> 1;
  const int g = lane >> 2, tig = lane & 3;
  const int m0 = blockIdx.y * 128, n0 = blockIdx.x * 128;

  float    acc [4][4][4] = {};
  uint32_t acc2[4][4][2] = {};
  const int a_row  = wm*64 + (lane & 7) + ((lane >> 3) & 1) * 8;
  const int a_koff = (lane & 16) ? 8 : 0;
  const int b_row  = (lane & 7) + ((lane >> 3) & 1) * 8;
  const int b_noff = wn*32 + ((lane & 16) ? 8 : 0);

  #pragma unroll
  for (int i = 0; i < 2; i++){
    int idx = tid + 256*i;
    int r = idx >> 2, c8 = (idx & 3) * 8;
    *(uint4*)&smh[OFF_AH + r*AROW + c8] = *(const uint4*)&Ah[(size_t)(m0+r)*K + c8];
    *(uint4*)&smh[OFF_AL + r*AROW + c8] = *(const uint4*)&Al[(size_t)(m0+r)*K + c8];
    int row = idx >> 4, nc = (idx & 15) * 8;
    *(uint4*)&smh[OFF_BH + row*BROW + nc] = *(const uint4*)&Wh[(size_t)row*N + n0 + nc];
    if (TERMS == 3)
      *(uint4*)&smh[OFF_BL + row*BROW + nc] = *(const uint4*)&Wl[(size_t)row*N + n0 + nc];
  }
  __syncthreads();

  const int nkt = K >> 5;
  for (int kt = 0; kt < nkt; kt++){
    uint4 rAh[2], rAl[2], rBh[2], rBl[2];
    const bool pf = (kt + 1 < nkt);
    if (pf){
      int k0 = (kt + 1) << 5;
      #pragma unroll
      for (int i = 0; i < 2; i++){
        int idx = tid + 256*i;
        int r = idx >> 2, c8 = (idx & 3) * 8;
        rAh[i] = *(const uint4*)&Ah[(size_t)(m0+r)*K + k0 + c8];
        rAl[i] = *(const uint4*)&Al[(size_t)(m0+r)*K + k0 + c8];
        int row = idx >> 4, nc = (idx & 15) * 8;
        rBh[i] = *(const uint4*)&Wh[(size_t)(k0+row)*N + n0 + nc];
        if (TERMS == 3)
          rBl[i] = *(const uint4*)&Wl[(size_t)(k0+row)*N + n0 + nc];
      }
    }
    const uint32_t bufb = smb + (uint32_t)(kt & 1) * (BUF_H * 2);

    #pragma unroll
    for (int ks = 0; ks < 2; ks++){
      uint32_t ah[4][4], al[4][4], bh[4][2], bl[4][2];
      #pragma unroll
      for (int mt = 0; mt < 4; mt++){
        uint32_t ad = bufb + (uint32_t)((a_row + mt*16)*AROW + ks*16 + a_koff) * 2;
        ldmat4(ah[mt], ad + OFF_AH*2);
        ldmat4(al[mt], ad + OFF_AL*2);
      }
      #pragma unroll
      for (int ntp = 0; ntp < 2; ntp++){
        uint32_t bd = bufb + (uint32_t)((b_row + ks*16)*BROW + b_noff + ntp*16) * 2;
        uint32_t th[4];
        ldmat4t(th, bd + OFF_BH*2);
        bh[ntp*2][0]=th[0]; bh[ntp*2][1]=th[1]; bh[ntp*2+1][0]=th[2]; bh[ntp*2+1][1]=th[3];
        if (TERMS == 3){
          uint32_t tl[4];
          ldmat4t(tl, bd + OFF_BL*2);
          bl[ntp*2][0]=tl[0]; bl[ntp*2][1]=tl[1]; bl[ntp*2+1][0]=tl[2]; bl[ntp*2+1][1]=tl[3];
        }
      }
      #pragma unroll
      for (int mt = 0; mt < 4; mt++)
        #pragma unroll
        for (int nt = 0; nt < 4; nt++){
          mma_f16(acc[mt][nt], ah[mt], bh[nt]);
          mma_f16acc(acc2[mt][nt], al[mt], bh[nt]);
          if (TERMS == 3) mma_f16acc(acc2[mt][nt], ah[mt], bl[nt]);
        }
    }

    if (pf){
      __half* dst = smh + ((kt + 1) & 1) * BUF_H;
      #pragma unroll
      for (int i = 0; i < 2; i++){
        int idx = tid + 256*i;
        int r = idx >> 2, c8 = (idx & 3) * 8;
        *(uint4*)&dst[OFF_AH + r*AROW + c8] = rAh[i];
        *(uint4*)&dst[OFF_AL + r*AROW + c8] = rAl[i];
        int row = idx >> 4, nc = (idx & 15) * 8;
        *(uint4*)&dst[OFF_BH + row*BROW + nc] = rBh[i];
        if (TERMS == 3)
          *(uint4*)&dst[OFF_BL + row*BROW + nc] = rBl[i];
      }
    }
    __syncthreads();
  }

  #pragma unroll
  for (int mt = 0; mt < 4; mt++){
    int r0 = m0 + wm*64 + mt*16 + g;
    #pragma unroll
    for (int nt = 0; nt < 4; nt++){
      int c = n0 + wn*32 + nt*8 + tig*2;
      float b0 = bias[c], b1 = bias[c+1];
      __half2 c01 = *(__half2*)&acc2[mt][nt][0];
      __half2 c23 = *(__half2*)&acc2[mt][nt][1];
      float2 v0, v1;
      v0.x = acc[mt][nt][0] + LOSCL*__low2float (c01) + b0;
      v0.y = acc[mt][nt][1] + LOSCL*__high2float(c01) + b1;
      v1.x = acc[mt][nt][2] + LOSCL*__low2float (c23) + b0;
      v1.y = acc[mt][nt][3] + LOSCL*__high2float(c23) + b1;
      if (ACT == 1){
        v0.x = 0.5f*v0.x*(1.0f + erff(v0.x*0.70710678118654752440f));
        v0.y = 0.5f*v0.y*(1.0f + erff(v0.y*0.70710678118654752440f));
        v1.x = 0.5f*v1.x*(1.0f + erff(v1.x*0.70710678118654752440f));
        v1.y = 0.5f*v1.y*(1.0f + erff(v1.y*0.70710678118654752440f));
      }
      if (OUTMODE == 0){
        *(float2*)&C[(size_t)r0*N + c]     = v0;
        *(float2*)&C[(size_t)(r0+8)*N + c] = v1;
      } else {
        __half h0,l0,h1,l1;
        split2(v0.x,h0,l0); split2(v0.y,h1,l1);
        *(__half2*)&Ch[(size_t)r0*N + c] = __halves2half2(h0,h1);
        *(__half2*)&Cl[(size_t)r0*N + c] = __halves2half2(l0,l1);
        split2(v1.x,h0,l0); split2(v1.y,h1,l1);
        *(__half2*)&Ch[(size_t)(r0+8)*N + c] = __halves2half2(h0,h1);
        *(__half2*)&Cl[(size_t)(r0+8)*N + c] = __halves2half2(l0,l1);
      }
    }
  }
}

// ======================= attention scores via mma =======================
// FULL=1 (layer 0): 3-term, fp32 S out.  FULL=0: 2-term, fp16 logits out.
#define S2_ROW 72
#define S2_AH 0
#define S2_AL (128*S2_ROW)
#define S2_BH (2*128*S2_ROW)
#define S2_BL (3*128*S2_ROW)
#define S2_SMEM (4*128*S2_ROW*2)

template<int FULL>
__global__ void __launch_bounds__(256) attn_scores_mma(
    const __half* __restrict__ qh, const __half* __restrict__ ql,
    const __half* __restrict__ kh, const __half* __restrict__ kl,
    int qs, const int* __restrict__ mix, float* __restrict__ S,
    __half* __restrict__ Slog){
  extern __shared__ __half smh[];
  const uint32_t smb = smem_u32(smh);
  const int bh = blockIdx.z, b = bh / HH, h = bh % HH;
  const int kb = mix ? mix[b] : b;
  const int i0 = blockIdx.y*128, j0 = blockIdx.x*128;
  const int tid = threadIdx.x, lane = tid & 31, wid = tid >> 5;
  const int wm = wid & 1, wn = wid >> 1;
  const int g = lane >> 2, tig = lane & 3;

  #pragma unroll
  for (int it = 0; it < 4; it++){
    int idx = tid + 256*it;
    int r = idx >> 3, c8 = (idx & 7) * 8;
    size_t qa = (size_t)(b *LL + i0 + r)*qs + h*KDIM + c8;
    size_t ka = (size_t)(kb*LL + j0 + r)*qs + h*KDIM + c8;
    *(uint4*)&smh[S2_AH + r*S2_ROW + c8] = *(const uint4*)&qh[qa];
    *(uint4*)&smh[S2_AL + r*S2_ROW + c8] = *(const uint4*)&ql[qa];
    *(uint4*)&smh[S2_BH + r*S2_ROW + c8] = *(const uint4*)&kh[ka];
    if (FULL)
      *(uint4*)&smh[S2_BL + r*S2_ROW + c8] = *(const uint4*)&kl[ka];
  }
  __syncthreads();

  float acc [4][4][4] = {};
  float acc2[4][4][4] = {};
  const int a_row  = wm*64 + (lane & 7) + ((lane >> 3) & 1) * 8;
  const int a_koff = (lane & 16) ? 8 : 0;
  const int b_nadd = wn*32 + ((lane >> 4) << 3) + (lane & 7);
  const int b_kadd = (lane & 8);

  #pragma unroll
  for (int ks = 0; ks < 4; ks++){
    uint32_t ah[4][4], al[4][4], bhf[4][2], blf[4][2];
    #pragma unroll
    for (int mt = 0; mt < 4; mt++){
      uint32_t ad = smb + (uint32_t)((a_row + mt*16)*S2_ROW + ks*16 + a_koff) * 2;
      ldmat4(ah[mt], ad + S2_AH*2);
      ldmat4(al[mt], ad + S2_AL*2);
    }
    #pragma unroll
    for (int ntp = 0; ntp < 2; ntp++){
      uint32_t bd = smb + (uint32_t)((b_nadd + ntp*16)*S2_ROW + ks*16 + b_kadd) * 2;
      uint32_t th[4];
      ldmat4(th, bd + S2_BH*2);
      bhf[ntp*2][0]=th[0]; bhf[ntp*2][1]=th[1]; bhf[ntp*2+1][0]=th[2]; bhf[ntp*2+1][1]=th[3];
      if (FULL){
        uint32_t tl[4];
        ldmat4(tl, bd + S2_BL*2);
        blf[ntp*2][0]=tl[0]; blf[ntp*2][1]=tl[1]; blf[ntp*2+1][0]=tl[2]; blf[ntp*2+1][1]=tl[3];
      }
    }
    #pragma unroll
    for (int mt = 0; mt < 4; mt++)
      #pragma unroll
      for (int nt = 0; nt < 4; nt++){
        mma_f16(acc [mt][nt], ah[mt], bhf[nt]);
        mma_f16(acc2[mt][nt], al[mt], bhf[nt]);
        if (FULL) mma_f16(acc2[mt][nt], ah[mt], blf[nt]);
      }
  }

  #pragma unroll
  for (int mt = 0; mt < 4; mt++){
    int r0 = i0 + wm*64 + mt*16 + g;
    #pragma unroll
    for (int nt = 0; nt < 4; nt++){
      int c = j0 + wn*32 + nt*8 + tig*2;
      float2 v0, v1;
      v0.x = (acc[mt][nt][0] + LOSCL*acc2[mt][nt][0]) * 0.125f;
      v0.y = (acc[mt][nt][1] + LOSCL*acc2[mt][nt][1]) * 0.125f;
      v1.x = (acc[mt][nt][2] + LOSCL*acc2[mt][nt][2]) * 0.125f;
      v1.y = (acc[mt][nt][3] + LOSCL*acc2[mt][nt][3]) * 0.125f;
      if (FULL){
        float* sbase = S + (size_t)bh*LL*LL;
        *(float2*)&sbase[(size_t)r0*LL + c]     = v0;
        *(float2*)&sbase[(size_t)(r0+8)*LL + c] = v1;
      } else {
        __half* lbase = Slog + (size_t)bh*LL*LL;
        *(__half2*)&lbase[(size_t)r0*LL + c]     = __halves2half2(__float2half_rn(v0.x), __float2half_rn(v0.y));
        *(__half2*)&lbase[(size_t)(r0+8)*LL + c] = __halves2half2(__float2half_rn(v1.x), __float2half_rn(v1.y));
      }
    }
  }
}

// ======================= O = P @ V via mma, P single fp16 (exact 2-term) =======================
#define V_AROW 40
#define V_BROW 72
#define V_A  0
#define V_BH (128*V_AROW)
#define V_BL (128*V_AROW + 32*V_BROW)
#define V_BUF (128*V_AROW + 2*32*V_BROW)
#define V_SMEM (2*V_BUF*2)

__global__ void __launch_bounds__(256) attn_av_mma(
    const __half* __restrict__ Sp,
    const __half* __restrict__ vh, const __half* __restrict__ vl, int vs,
    __half* __restrict__ oh, __half* __restrict__ ol){
  extern __shared__ __half smh[];
  const uint32_t smb = smem_u32(smh);
  const int bh = blockIdx.y, b = bh / HH, h = bh % HH;
  const int i0 = blockIdx.x*128;
  const int tid = threadIdx.x, lane = tid & 31, wid = tid >> 5;
  const int wm = wid & 3, wn = wid >> 2;
  const int g = lane >> 2, tig = lane & 3;
  const __half* spb = Sp + (size_t)bh*LL*LL;

  float acc [2][4][4] = {};
  float acc2[2][4][4] = {};
  const int a_row  = wm*32 + (lane & 7) + ((lane >> 3) & 1) * 8;
  const int a_koff = (lane & 16) ? 8 : 0;
  const int b_row  = (lane & 7) + ((lane >> 3) & 1) * 8;
  const int b_noff = wn*32 + ((lane & 16) ? 8 : 0);

  #pragma unroll
  for (int i = 0; i < 2; i++){
    int idx = tid + 256*i;
    int r = idx >> 2, c8 = (idx & 3) * 8;
    *(uint4*)&smh[V_A + r*V_AROW + c8] = *(const uint4*)&spb[(size_t)(i0 + r)*LL + c8];
  }
  {
    int r = tid >> 3, c8 = (tid & 7) * 8;
    size_t va = (size_t)(b*LL + r)*vs + h*KDIM + c8;
    *(uint4*)&smh[V_BH + r*V_BROW + c8] = *(const uint4*)&vh[va];
    *(uint4*)&smh[V_BL + r*V_BROW + c8] = *(const uint4*)&vl[va];
  }
  __syncthreads();

  for (int kt = 0; kt < 16; kt++){
    uint4 rA[2], rBh, rBl;
    const bool pf = (kt + 1 < 16);
    if (pf){
      int k0 = (kt + 1) << 5;
      #pragma unroll
      for (int i = 0; i < 2; i++){
        int idx = tid + 256*i;
        int r = idx >> 2, c8 = (idx & 3) * 8;
        rA[i] = *(const uint4*)&spb[(size_t)(i0 + r)*LL + k0 + c8];
      }
      int r = tid >> 3, c8 = (tid & 7) * 8;
      size_t va = (size_t)(b*LL + k0 + r)*vs + h*KDIM + c8;
      rBh = *(const uint4*)&vh[va];
      rBl = *(const uint4*)&vl[va];
    }
    const uint32_t bufb = smb + (uint32_t)(kt & 1) * (V_BUF * 2);

    #pragma unroll
    for (int ks = 0; ks < 2; ks++){
      uint32_t ah[2][4], bhf[4][2], blf[4][2];
      #pragma unroll
      for (int mt = 0; mt < 2; mt++){
        uint32_t ad = bufb + (uint32_t)((a_row + mt*16)*V_AROW + ks*16 + a_koff) * 2;
        ldmat4(ah[mt], ad + V_A*2);
      }
      #pragma unroll
      for (int ntp = 0; ntp < 2; ntp++){
        uint32_t bd = bufb + (uint32_t)((b_row + ks*16)*V_BROW + b_noff + ntp*16) * 2;
        uint32_t th[4], tl[4];
        ldmat4t(th, bd + V_BH*2);
        ldmat4t(tl, bd + V_BL*2);
        bhf[ntp*2][0]=th[0]; bhf[ntp*2][1]=th[1]; bhf[ntp*2+1][0]=th[2]; bhf[ntp*2+1][1]=th[3];
        blf[ntp*2][0]=tl[0]; blf[ntp*2][1]=tl[1]; blf[ntp*2+1][0]=tl[2]; blf[ntp*2+1][1]=tl[3];
      }
      #pragma unroll
      for (int mt = 0; mt < 2; mt++)
        #pragma unroll
        for (int nt = 0; nt < 4; nt++){
          mma_f16(acc [mt][nt], ah[mt], bhf[nt]);
          mma_f16(acc2[mt][nt], ah[mt], blf[nt]);
        }
    }

    if (pf){
      __half* dst = smh + ((kt + 1) & 1) * V_BUF;
      #pragma unroll
      for (int i = 0; i < 2; i++){
        int idx = tid + 256*i;
        int r = idx >> 2, c8 = (idx & 3) * 8;
        *(uint4*)&dst[V_A + r*V_AROW + c8] = rA[i];
      }
      int r = tid >> 3, c8 = (tid & 7) * 8;
      *(uint4*)&dst[V_BH + r*V_BROW + c8] = rBh;
      *(uint4*)&dst[V_BL + r*V_BROW + c8] = rBl;
    }
    __syncthreads();
  }

  #pragma unroll
  for (int mt = 0; mt < 2; mt++){
    int r0 = i0 + wm*32 + mt*16 + g;
    #pragma unroll
    for (int nt = 0; nt < 4; nt++){
      int c = wn*32 + nt*8 + tig*2;
      float2 v0, v1;
      v0.x = acc[mt][nt][0] + LOSCL*acc2[mt][nt][0];
      v0.y = acc[mt][nt][1] + LOSCL*acc2[mt][nt][1];
      v1.x = acc[mt][nt][2] + LOSCL*acc2[mt][nt][2];
      v1.y = acc[mt][nt][3] + LOSCL*acc2[mt][nt][3];
      size_t o0 = (size_t)(b*LL + r0)*DD + h*KDIM + c;
      size_t o1 = (size_t)(b*LL + r0 + 8)*DD + h*KDIM + c;
      __half h0,l0,h1,l1;
      split2(v0.x,h0,l0); split2(v0.y,h1,l1);
      *(__half2*)&oh[o0] = __halves2half2(h0,h1);
      *(__half2*)&ol[o0] = __halves2half2(l0,l1);
      split2(v1.x,h0,l0); split2(v1.y,h1,l1);
      *(__half2*)&oh[o1] = __halves2half2(h0,h1);
      *(__half2*)&ol[o1] = __halves2half2(l0,l1);
    }
  }
}

// ---------------- reductions ----------------
__device__ __forceinline__ float warpSum(float v){
  #pragma unroll
  for (int o=16;o;o>>=1) v += __shfl_xor_sync(0xffffffffu, v, o);
  return v;
}
__device__ __forceinline__ float warpMax(float v){
  #pragma unroll
  for (int o=16;o;o>>=1) v = fmaxf(v, __shfl_xor_sync(0xffffffffu, v, o));
  return v;
}
template<int NWARP>
__device__ __forceinline__ float blockSum(float v, float* sh){
  int lane = threadIdx.x & 31, w = threadIdx.x >> 5;
  v = warpSum(v);
  if (lane == 0) sh[w] = v;
  __syncthreads();
  float r = (lane < NWARP) ? sh[lane] : 0.f;
  r = warpSum(r);
  __syncthreads();
  return r;
}
template<int NWARP>
__device__ __forceinline__ float blockMax(float v, float* sh){
  int lane = threadIdx.x & 31, w = threadIdx.x >> 5;
  v = warpMax(v);
  if (lane == 0) sh[w] = v;
  __syncthreads();
  float r = (lane < NWARP) ? sh[lane] : -INFINITY;
  r = warpMax(r);
  __syncthreads();
  return r;
}

// ---------------- masked softmax, warp-per-row ----------------
template<int FULL>
__global__ void __launch_bounds__(512) softmax512(float* __restrict__ S,
    const __half* __restrict__ Slog, __half* __restrict__ Sp,
    const float* __restrict__ amask, const int* __restrict__ mix){
  const int row = blockIdx.x*16 + (threadIdx.x >> 5);
  const int lane = threadIdx.x & 31;
  const int bh = row >> 9;
  const int b  = bh / HH;
  const int kb = mix ? mix[b] : b;
  float* sr = S + (size_t)row*LL;
  const __half* lr = Slog + (size_t)row*LL;
  __half* spr = Sp + (size_t)row*LL;
  const float* mr = amask + (size_t)kb*LL;

  float4 v4[4], m4[4];
  float mx = -INFINITY;
  #pragma unroll
  for (int c = 0; c < 4; c++){
    int j = lane*4 + c*128;
    if (FULL){
      v4[c] = *(const float4*)&sr[j];
    } else {
      uint2 hv = *(const uint2*)&lr[j];
      const __half* ph = (const __half*)&hv;
      v4[c].x = __half2float(ph[0]); v4[c].y = __half2float(ph[1]);
      v4[c].z = __half2float(ph[2]); v4[c].w = __half2float(ph[3]);
    }
    m4[c] = *(const float4*)&mr[j];
    v4[c].x *= m4[c].x; v4[c].y *= m4[c].y; v4[c].z *= m4[c].z; v4[c].w *= m4[c].w;
    mx = fmaxf(mx, fmaxf(fmaxf(v4[c].x, v4[c].y), fmaxf(v4[c].z, v4[c].w)));
  }
  mx = warpMax(mx);
  float s = 0.f;
  #pragma unroll
  for (int c = 0; c < 4; c++){
    v4[c].x = expf(v4[c].x - mx)*m4[c].x;
    v4[c].y = expf(v4[c].y - mx)*m4[c].y;
    v4[c].z = expf(v4[c].z - mx)*m4[c].z;
    v4[c].w = expf(v4[c].w - mx)*m4[c].w;
    s += v4[c].x + v4[c].y + v4[c].z + v4[c].w;
  }
  s = warpSum(s);
  if (s == 0.f) s = 1.f;
  float inv = 1.f/s;
  #pragma unroll
  for (int c = 0; c < 4; c++){
    int j = lane*4 + c*128;
    float4 p;
    p.x = v4[c].x*inv; p.y = v4[c].y*inv; p.z = v4[c].z*inv; p.w = v4[c].w*inv;
    if (FULL) *(float4*)&sr[j] = p;
    __half h4[4];
    h4[0] = __float2half_rn(p.x); h4[1] = __float2half_rn(p.y);
    h4[2] = __float2half_rn(p.z); h4[3] = __float2half_rn(p.w);
    *(uint2*)&spr[j] = *(uint2*)h4;
  }
}

// ---------------- cross-sim argmax ----------------
__global__ void __launch_bounds__(256) cross_argmax(const float* __restrict__ S,
    int* __restrict__ pos){
  const int i = blockIdx.x, b = blockIdx.y;
  if (i == 0 || i == LL-1){
    if (threadIdx.x == 0) pos[b*LL + i] = i;
    return;
  }
  __shared__ float sval[256];
  __shared__ int   sidx[256];
  float best = -1.f; int bestj = 0;
  for (int j = threadIdx.x; j < LL; j += 256){
    if (j < 1 || j > LL-2) continue;
    float cs = -INFINITY;
    #pragma unroll
    for (int h=0; h<HH; h++)
      cs = fmaxf(cs, S[((size_t)(b*HH+h)*LL + i)*LL + j]);
    if (cs > best || (cs == best && j > bestj)){ best = cs; bestj = j; }
  }
  sval[threadIdx.x]=best; sidx[threadIdx.x]=bestj;
  __syncthreads();
  for (int s=128; s; s>>=1){
    if (threadIdx.x < s){
      float v2 = sval[threadIdx.x+s]; int j2 = sidx[threadIdx.x+s];
      if (v2 > sval[threadIdx.x] || (v2 == sval[threadIdx.x] && j2 > sidx[threadIdx.x])){
        sval[threadIdx.x]=v2; sidx[threadIdx.x]=j2;
      }
    }
    __syncthreads();
  }
  if (threadIdx.x == 0) pos[b*LL + i] = sidx[0];
}

// ---------------- mixup apply ----------------
__global__ void __launch_bounds__(256) mixup_apply(const float* __restrict__ h,
    const int* __restrict__ mix, const int* __restrict__ pos,
    const float* __restrict__ alphap, float* __restrict__ outh){
  const int t = blockIdx.x, b = t / LL;
  const float a = *alphap;
  const int mb = mix[b], p = pos[t];
  const float* cur = h + (size_t)t*DD;
  const float* src = h + (size_t)(mb*LL + p)*DD;
  float* dst = outh + (size_t)t*DD;
  for (int d = threadIdx.x; d < DD; d += 256)
    dst[d] = a*cur[d] + (1.f-a)*src[d];
}

__global__ void __launch_bounds__(256) copy_split(const float* __restrict__ src,
    float* __restrict__ dst, __half* __restrict__ dh, __half* __restrict__ dl, int n){
  int i = blockIdx.x*256 + threadIdx.x;
  if (i < n){
    float x = src[i];
    dst[i] = x;
    __half hi, lo; split2(x, hi, lo);
    dh[i] = hi; dl[i] = lo;
  }
}

// ---------------- embedding + LN ----------------
__global__ void __launch_bounds__(256) embed_ln(const int* __restrict__ ids,
    const float* __restrict__ we, const float* __restrict__ pe, const float* __restrict__ te,
    const float* __restrict__ w, const float* __restrict__ bprm,
    float* __restrict__ h, __half* __restrict__ hh, __half* __restrict__ hl){
  const int t = blockIdx.x, l = t % LL;
  __shared__ float red[8];
  const int id = ids[t];
  float xs[3]; float s = 0.f;
  #pragma unroll
  for (int r=0;r<3;r++){
    int d = threadIdx.x + 256*r;
    float x = we[(size_t)id*DD + d] + pe[(size_t)l*DD + d] + te[d];
    xs[r]=x; s += x;
  }
  float mu = blockSum<8>(s, red) * (1.f/DD);
  float vs = 0.f;
  #pragma unroll
  for (int r=0;r<3;r++){ float c = xs[r]-mu; vs += c*c; }
  float var = blockSum<8>(vs, red) * (1.f/DD);
  float rstd = rsqrtf(var + 1e-12f);
  #pragma unroll
  for (int r=0;r<3;r++){
    int d = threadIdx.x + 256*r;
    float y = (xs[r]-mu)*rstd*w[d] + bprm[d];
    h[(size_t)t*DD + d] = y;
    __half hi, lo; split2(y, hi, lo);
    hh[(size_t)t*DD + d] = hi; hl[(size_t)t*DD + d] = lo;
  }
}

// ---------------- h = LN(hin + res) ----------------
__global__ void __launch_bounds__(256) add_ln(const float* __restrict__ hin,
    const float* __restrict__ res, const float* __restrict__ w,
    const float* __restrict__ bprm, float* __restrict__ hout,
    __half* __restrict__ hh, __half* __restrict__ hl){
  const int t = blockIdx.x;
  __shared__ float red[8];
  float xs[3]; float s = 0.f;
  #pragma unroll
  for (int r=0;r<3;r++){
    int d = threadIdx.x + 256*r;
    float x = hin[(size_t)t*DD + d] + res[(size_t)t*DD + d];
    xs[r]=x; s += x;
  }
  float mu = blockSum<8>(s, red) * (1.f/DD);
  float vs = 0.f;
  #pragma unroll
  for (int r=0;r<3;r++){ float c = xs[r]-mu; vs += c*c; }
  float var = blockSum<8>(vs, red) * (1.f/DD);
  float rstd = rsqrtf(var + 1e-12f);
  #pragma unroll
  for (int r=0;r<3;r++){
    int d = threadIdx.x + 256*r;
    float y = (xs[r]-mu)*rstd*w[d] + bprm[d];
    hout[(size_t)t*DD + d] = y;
    __half hi, lo; split2(y, hi, lo);
    hh[(size_t)t*DD + d] = hi; hl[(size_t)t*DD + d] = lo;
  }
}

// ---------------- mean pool (two stage) ----------------
__global__ void __launch_bounds__(256) pool_part(const float* __restrict__ h,
    float* __restrict__ part){
  const int b = blockIdx.x, chunk = blockIdx.y;
  float acc[3] = {0.f,0.f,0.f};
  for (int l = chunk*32; l < chunk*32 + 32; l++){
    const float* row = h + (size_t)(b*LL + l)*DD;
    #pragma unroll
    for (int r=0;r<3;r++) acc[r] += row[threadIdx.x + 256*r];
  }
  #pragma unroll
  for (int r=0;r<3;r++)
    part[((size_t)b*16 + chunk)*DD + threadIdx.x + 256*r] = acc[r];
}
__global__ void __launch_bounds__(256) pool_final(const float* __restrict__ part,
    float* __restrict__ p){
  const int b = blockIdx.x;
  float acc[3] = {0.f,0.f,0.f};
  for (int c = 0; c < 16; c++){
    #pragma unroll
    for (int r=0;r<3;r++)
      acc[r] += part[((size_t)b*16 + c)*DD + threadIdx.x + 256*r];
  }
  #pragma unroll
  for (int r=0;r<3;r++)
    p[(size_t)b*DD + threadIdx.x + 256*r] = acc[r]*(1.f/LL);
}

// ---------------- classifier head ----------------
__global__ void __launch_bounds__(128) head_kernel(const float* __restrict__ p,
    const float* __restrict__ c1w, const float* __restrict__ c1b,
    const float* __restrict__ c2w, const float* __restrict__ c2b,
    float* __restrict__ out){
  const int b = blockIdx.x;
  __shared__ float ps[DD];
  __shared__ float c1s[128];
  for (int d = threadIdx.x; d < DD; d += 128) ps[d] = p[(size_t)b*DD + d];
  __syncthreads();
  const int t = threadIdx.x;
  float s = c1b[t];
  for (int d = 0; d < DD; d++) s += ps[d]*c1w[(size_t)d*128 + t];
  c1s[t] = tanhf(s);
  __syncthreads();
  if (t < NCLS){
    float o = c2b[t];
    #pragma unroll
    for (int j=0;j<128;j++) o += c1s[j]*c2w[j*NCLS + t];
    out[b*NCLS + t] = o;
  }
}

// ---------------- launcher ----------------
extern "C" void kernel_launch(void* const* d_in, const int* in_sizes, int n_in,
                              void* d_out, int out_size){
  const int*   ids   = (const int*)  d_in[0];
  const float* amask = (const float*)d_in[1];
  const int*   mix   = (const int*)  d_in[2];
  const float* alpha = (const float*)d_in[6];
  const float* we    = (const float*)d_in[7];
  const float* pe    = (const float*)d_in[8];
  const float* te    = (const float*)d_in[9];
  const float* elnw  = (const float*)d_in[10];
  const float* elnb  = (const float*)d_in[11];
  const float* Wq = (const float*)d_in[12]; const float* bq = (const float*)d_in[13];
  const float* Wk = (const float*)d_in[14]; const float* bk = (const float*)d_in[15];
  const float* Wv = (const float*)d_in[16]; const float* bv = (const float*)d_in[17];
  const float* Wo = (const float*)d_in[18]; const float* bo = (const float*)d_in[19];
  const float* l1w = (const float*)d_in[20]; const float* l1b = (const float*)d_in[21];
  const float* Wf1 = (const float*)d_in[22]; const float* bf1 = (const float*)d_in[23];
  const float* Wf2 = (const float*)d_in[24]; const float* bf2 = (const float*)d_in[25];
  const float* l2w = (const float*)d_in[26]; const float* l2b = (const float*)d_in[27];
  const float* c1w = (const float*)d_in[28]; const float* c1b = (const float*)d_in[29];
  const float* c2w = (const float*)d_in[30]; const float* c2b = (const float*)d_in[31];
  float* out = (float*)d_out;

  float *h,*t2,*sc,*pl,*part,*bqkv; int* mpos;
  cudaGetSymbolAddress((void**)&h,    g_h);
  cudaGetSymbolAddress((void**)&t2,   g_t2);
  cudaGetSymbolAddress((void**)&sc,   g_scores);
  cudaGetSymbolAddress((void**)&pl,   g_pooled);
  cudaGetSymbolAddress((void**)&part, g_part);
  cudaGetSymbolAddress((void**)&mpos, g_mixpos);
  cudaGetSymbolAddress((void**)&bqkv, g_bqkv);

  __half *hh,*hl,*qkvh,*qkvl,*oh,*ol,*t1h,*t1l,*Sp,*Slog;
  cudaGetSymbolAddress((void**)&hh,   g_hh);   cudaGetSymbolAddress((void**)&hl,   g_hl);
  cudaGetSymbolAddress((void**)&qkvh, g_qkvh); cudaGetSymbolAddress((void**)&qkvl, g_qkvl);
  cudaGetSymbolAddress((void**)&oh,   g_oh);   cudaGetSymbolAddress((void**)&ol,   g_ol);
  cudaGetSymbolAddress((void**)&t1h,  g_t1h);  cudaGetSymbolAddress((void**)&t1l,  g_t1l);
  cudaGetSymbolAddress((void**)&Sp,   g_Sp);   cudaGetSymbolAddress((void**)&Slog, g_Slog);

  __half *Wqkvh,*Wqkvl,*Woh,*Wol,*Wf1h,*Wf1l,*Wf2h,*Wf2l;
  cudaGetSymbolAddress((void**)&Wqkvh, g_Wqkvh); cudaGetSymbolAddress((void**)&Wqkvl, g_Wqkvl);
  cudaGetSymbolAddress((void**)&Woh,   g_Woh);   cudaGetSymbolAddress((void**)&Wol,   g_Wol);
  cudaGetSymbolAddress((void**)&Wf1h,  g_Wf1h);  cudaGetSymbolAddress((void**)&Wf1l,  g_Wf1l);
  cudaGetSymbolAddress((void**)&Wf2h,  g_Wf2h);  cudaGetSymbolAddress((void**)&Wf2l,  g_Wf2l);

  static int attrset = 0;
  if (!attrset){
    cudaFuncSetAttribute(gemm_hh<0,0,2>, cudaFuncAttributeMaxDynamicSharedMemorySize, GEMM_SMEM);
    cudaFuncSetAttribute(gemm_hh<1,1,2>, cudaFuncAttributeMaxDynamicSharedMemorySize, GEMM_SMEM);
    cudaFuncSetAttribute(gemm_hh<0,1,3>, cudaFuncAttributeMaxDynamicSharedMemorySize, GEMM_SMEM);
    cudaFuncSetAttribute(attn_scores_mma<0>, cudaFuncAttributeMaxDynamicSharedMemorySize, S2_SMEM);
    cudaFuncSetAttribute(attn_scores_mma<1>, cudaFuncAttributeMaxDynamicSharedMemorySize, S2_SMEM);
    cudaFuncSetAttribute(attn_av_mma,        cudaFuncAttributeMaxDynamicSharedMemorySize, V_SMEM);
    attrset = 1;
  }

  // prep
  {
    int tq4 = NLAY*DD*QKVN/4;
    pack_qkv<<<(tq4+255)/256, 256>>>((const float4*)Wq, (const float4*)Wk,
                                     (const float4*)Wv, (__half2*)Wqkvh, (__half2*)Wqkvl, tq4);
    pack_bias<<<(NLAY*QKVN+255)/256, 256>>>(bq, bk, bv, bqkv, NLAY*QKVN);
  }
  embed_ln<<<NTOK,256>>>(ids, we, pe, te, elnw, elnb, h, hh, hl);

  bool wprep = false;
  for (int layer = 0; layer < NLAY; layer++){
    const size_t od3 = (size_t)layer*DD*QKVN;
    const size_t od  = (size_t)layer*DD*DD;
    const size_t of  = (size_t)layer*DD*FFD;
    const float* bqkv_l = bqkv + (size_t)layer*QKVN;
    const float* bo_l   = bo   + (size_t)layer*DD;
    const float* bf1_l  = bf1  + (size_t)layer*FFD;
    const float* bf2_l  = bf2  + (size_t)layer*DD;
    dim3 gdd(DD/128, NTOK/128), gdf(FFD/128, NTOK/128), gqkv(QKVN/128, NTOK/128);

    if (layer == 0){
      gemm_hh<0,1,3><<<dim3(12, NTOK/128), 256, GEMM_SMEM>>>(hh, hl, Wqkvh+od3, Wqkvl+od3,
          bqkv_l, nullptr, qkvh, qkvl, NTOK, QKVN, DD);
      if (!wprep){
        int n4s = NLAY*DD*DD/4;
        split_w<<<(n4s+255)/256, 256>>>((const float4*)Wo, (__half2*)Woh, (__half2*)Wol, n4s);
        int n4f = NLAY*DD*FFD/4;
        split_w2<<<dim3((n4f+255)/256, 2), 256>>>((const float4*)Wf1, (__half2*)Wf1h, (__half2*)Wf1l,
                                                  (const float4*)Wf2, (__half2*)Wf2h, (__half2*)Wf2l, n4f);
        wprep = true;
      }
      attn_scores_mma<1><<<dim3(LL/128, LL/128, BB*HH), 256, S2_SMEM>>>(
          qkvh, qkvl, qkvh+DD, qkvl+DD, QKVN, mix, sc, nullptr);
      softmax512<1><<<BB*HH*LL/16, 512>>>(sc, nullptr, Sp, amask, mix);
      cross_argmax<<<dim3(LL, BB), 256>>>(sc, mpos);
      mixup_apply<<<NTOK, 256>>>(h, mix, mpos, alpha, t2);
      copy_split<<<(NTOK*DD + 255)/256, 256>>>(t2, h, hh, hl, NTOK*DD);
    }

    gemm_hh<0,1,3><<<gqkv, 256, GEMM_SMEM>>>(hh, hl, Wqkvh+od3, Wqkvl+od3,
        bqkv_l, nullptr, qkvh, qkvl, NTOK, QKVN, DD);

    attn_scores_mma<0><<<dim3(LL/128, LL/128, BB*HH), 256, S2_SMEM>>>(
        qkvh, qkvl, qkvh+DD, qkvl+DD, QKVN, nullptr, nullptr, Slog);
    softmax512<0><<<BB*HH*LL/16, 512>>>(nullptr, Slog, Sp, amask, nullptr);
    attn_av_mma<<<dim3(LL/128, BB*HH), 256, V_SMEM>>>(Sp, qkvh+2*DD, qkvl+2*DD, QKVN, oh, ol);

    gemm_hh<0,0,2><<<gdd, 256, GEMM_SMEM>>>(oh, ol, Woh+od, Wol+od, bo_l, t2,
        nullptr, nullptr, NTOK, DD, DD);
    add_ln<<<NTOK, 256>>>(h, t2, l1w + (size_t)layer*DD, l1b + (size_t)layer*DD, h, hh, hl);

    gemm_hh<1,1,2><<<gdf, 256, GEMM_SMEM>>>(hh, hl, Wf1h+of, Wf1l+of, bf1_l,
        nullptr, t1h, t1l, NTOK, FFD, DD);
    gemm_hh<0,0,2><<<gdd, 256, GEMM_SMEM>>>(t1h, t1l, Wf2h+of, Wf2l+of, bf2_l, t2,
        nullptr, nullptr, NTOK, DD, FFD);
    add_ln<<<NTOK, 256>>>(h, t2, l2w + (size_t)layer*DD, l2b + (size_t)layer*DD, h, hh, hl);
  }

  pool_part<<<dim3(BB,16), 256>>>(h, part);
  pool_final<<<BB, 256>>>(part, pl);
  head_kernel<<<BB, 128>>>(pl, c1w, c1b, c2w, c2b, out);
}